// round 3
// baseline (speedup 1.0000x reference)
#include <cuda_runtime.h>
#include <cstdint>

#define D      128
#define HEADS  8
#define HD     16
#define KN     16
#define MPAD   50048   // 391 * 128 (grid-padded row count)

// Scratch (device globals; allocation is forbidden)
__device__ float g_Q[(size_t)MPAD * D];
__device__ float g_K[(size_t)MPAD * D];
__device__ float g_V[(size_t)MPAD * D];
__device__ float g_A[(size_t)MPAD * D];

// ---------------------------------------------------------------------------
// Generic fp32 GEMM + bias: C[M,128] = A[M,128] @ W[128,128] + b[128]
// 128x128 CTA tile, 256 threads, 8x8 register blocking.
// ---------------------------------------------------------------------------
__global__ __launch_bounds__(256, 2)
void gemm_bias_128(const float* __restrict__ A, const float* __restrict__ W,
                   const float* __restrict__ bias, float* __restrict__ C, int M)
{
    __shared__ float As[128][33];   // +1 pad: conflict-free column reads
    __shared__ float Bs[32][128];

    const int tid = threadIdx.x;
    const int tm  = tid >> 4;      // 0..15 -> rows tm*8..tm*8+7
    const int tn  = tid & 15;      // 0..15 -> cols tn*8..tn*8+7
    const int rowBase = blockIdx.x * 128;

    float acc[8][8];
#pragma unroll
    for (int i = 0; i < 8; i++)
#pragma unroll
        for (int j = 0; j < 8; j++) acc[i][j] = 0.f;

    for (int kt = 0; kt < D; kt += 32) {
        // A tile: 128 rows x 32 cols = 1024 float4, 4 per thread
#pragma unroll
        for (int i = 0; i < 4; i++) {
            int f4 = tid + i * 256;
            int m  = f4 >> 3;
            int kk = (f4 & 7) << 2;
            float4 v = make_float4(0.f, 0.f, 0.f, 0.f);
            int gm = rowBase + m;
            if (gm < M) v = *(const float4*)(A + (size_t)gm * D + kt + kk);
            As[m][kk + 0] = v.x; As[m][kk + 1] = v.y;
            As[m][kk + 2] = v.z; As[m][kk + 3] = v.w;
        }
        // B tile: 32 rows x 128 cols = 1024 float4, 4 per thread
#pragma unroll
        for (int i = 0; i < 4; i++) {
            int f4 = tid + i * 256;
            int kk = f4 >> 5;
            int n  = (f4 & 31) << 2;
            *(float4*)&Bs[kk][n] = *(const float4*)(W + (size_t)(kt + kk) * D + n);
        }
        __syncthreads();

#pragma unroll
        for (int k = 0; k < 32; k++) {
            float a[8], b[8];
#pragma unroll
            for (int i = 0; i < 8; i++) a[i] = As[tm * 8 + i][k];
            *(float4*)&b[0] = *(const float4*)&Bs[k][tn * 8];
            *(float4*)&b[4] = *(const float4*)&Bs[k][tn * 8 + 4];
#pragma unroll
            for (int i = 0; i < 8; i++)
#pragma unroll
                for (int j = 0; j < 8; j++)
                    acc[i][j] = fmaf(a[i], b[j], acc[i][j]);
        }
        __syncthreads();
    }

#pragma unroll
    for (int i = 0; i < 8; i++) {
        int gm = rowBase + tm * 8 + i;
        if (gm < M) {
#pragma unroll
            for (int j4 = 0; j4 < 2; j4++) {
                int n0 = tn * 8 + j4 * 4;
                float4 o;
                o.x = acc[i][j4 * 4 + 0] + bias[n0 + 0];
                o.y = acc[i][j4 * 4 + 1] + bias[n0 + 1];
                o.z = acc[i][j4 * 4 + 2] + bias[n0 + 2];
                o.w = acc[i][j4 * 4 + 3] + bias[n0 + 3];
                *(float4*)(C + (size_t)gm * D + n0) = o;
            }
        }
    }
}

// ---------------------------------------------------------------------------
// Neighborhood attention: one warp per node.
// Lane l: head h = l>>2, quad-slot kq = l&3 handles neighbors kq*4..kq*4+3.
// Softmax over 16 neighbors = 4 local + shfl.xor(1,2) within the quad.
// NOTE: neighbors buffer is int32 (JAX x64-disabled downcasts jnp.int64).
// ---------------------------------------------------------------------------
__global__ __launch_bounds__(256)
void attn_kernel(const float* __restrict__ Q, const float* __restrict__ Km,
                 const float* __restrict__ Vm,
                 const int* __restrict__ nbr,
                 float* __restrict__ Out, int N)
{
    const int warp = (blockIdx.x * blockDim.x + threadIdx.x) >> 5;
    if (warp >= N) return;                 // warp-uniform exit
    const int lane = threadIdx.x & 31;
    const int h  = lane >> 2;
    const int kq = lane & 3;
    const int node = warp;

    const float* qp = Q + (size_t)node * D + h * HD;
    float4 q0 = *(const float4*)(qp + 0);
    float4 q1 = *(const float4*)(qp + 4);
    float4 q2 = *(const float4*)(qp + 8);
    float4 q3 = *(const float4*)(qp + 12);

    float s[4];
    int   ids[4];
#pragma unroll
    for (int j = 0; j < 4; j++) {
        int kk = kq * 4 + j;
        int id = nbr[(size_t)node * KN + kk];
        bool masked = (id < 0);
        // clamp into [0, N-1] for safety; reference clips at 0
        int cid = id < 0 ? 0 : (id >= N ? N - 1 : id);
        ids[j] = cid;
        if (masked) {
            s[j] = -1e9f;
        } else {
            const float* kp = Km + (size_t)cid * D + h * HD;
            float4 k0 = *(const float4*)(kp + 0);
            float4 k1 = *(const float4*)(kp + 4);
            float4 k2 = *(const float4*)(kp + 8);
            float4 k3 = *(const float4*)(kp + 12);
            float d = q0.x * k0.x + q0.y * k0.y + q0.z * k0.z + q0.w * k0.w
                    + q1.x * k1.x + q1.y * k1.y + q1.z * k1.z + q1.w * k1.w
                    + q2.x * k2.x + q2.y * k2.y + q2.z * k2.z + q2.w * k2.w
                    + q3.x * k3.x + q3.y * k3.y + q3.z * k3.z + q3.w * k3.w;
            s[j] = d * 0.25f;              // 1/sqrt(hd) = 1/4
        }
    }

    // max over 16 scores of this head
    float m = fmaxf(fmaxf(s[0], s[1]), fmaxf(s[2], s[3]));
    m = fmaxf(m, __shfl_xor_sync(0xffffffffu, m, 1));
    m = fmaxf(m, __shfl_xor_sync(0xffffffffu, m, 2));

    float e[4];
    float sum = 0.f;
#pragma unroll
    for (int j = 0; j < 4; j++) { e[j] = __expf(s[j] - m); sum += e[j]; }
    sum += __shfl_xor_sync(0xffffffffu, sum, 1);
    sum += __shfl_xor_sync(0xffffffffu, sum, 2);
    const float inv = 1.0f / sum;

    float4 a0 = make_float4(0.f, 0.f, 0.f, 0.f);
    float4 a1 = a0, a2 = a0, a3 = a0;
#pragma unroll
    for (int j = 0; j < 4; j++) {
        float w = e[j] * inv;              // exactly 0 for masked (exp underflow)
        const float* vp = Vm + (size_t)ids[j] * D + h * HD;
        float4 v0 = *(const float4*)(vp + 0);
        float4 v1 = *(const float4*)(vp + 4);
        float4 v2 = *(const float4*)(vp + 8);
        float4 v3 = *(const float4*)(vp + 12);
        a0.x = fmaf(w, v0.x, a0.x); a0.y = fmaf(w, v0.y, a0.y);
        a0.z = fmaf(w, v0.z, a0.z); a0.w = fmaf(w, v0.w, a0.w);
        a1.x = fmaf(w, v1.x, a1.x); a1.y = fmaf(w, v1.y, a1.y);
        a1.z = fmaf(w, v1.z, a1.z); a1.w = fmaf(w, v1.w, a1.w);
        a2.x = fmaf(w, v2.x, a2.x); a2.y = fmaf(w, v2.y, a2.y);
        a2.z = fmaf(w, v2.z, a2.z); a2.w = fmaf(w, v2.w, a2.w);
        a3.x = fmaf(w, v3.x, a3.x); a3.y = fmaf(w, v3.y, a3.y);
        a3.z = fmaf(w, v3.z, a3.z); a3.w = fmaf(w, v3.w, a3.w);
    }

    // reduce partial attended vectors across the quad (xor 1, then 2)
#pragma unroll
    for (int off = 1; off <= 2; off <<= 1) {
        a0.x += __shfl_xor_sync(0xffffffffu, a0.x, off);
        a0.y += __shfl_xor_sync(0xffffffffu, a0.y, off);
        a0.z += __shfl_xor_sync(0xffffffffu, a0.z, off);
        a0.w += __shfl_xor_sync(0xffffffffu, a0.w, off);
        a1.x += __shfl_xor_sync(0xffffffffu, a1.x, off);
        a1.y += __shfl_xor_sync(0xffffffffu, a1.y, off);
        a1.z += __shfl_xor_sync(0xffffffffu, a1.z, off);
        a1.w += __shfl_xor_sync(0xffffffffu, a1.w, off);
        a2.x += __shfl_xor_sync(0xffffffffu, a2.x, off);
        a2.y += __shfl_xor_sync(0xffffffffu, a2.y, off);
        a2.z += __shfl_xor_sync(0xffffffffu, a2.z, off);
        a2.w += __shfl_xor_sync(0xffffffffu, a2.w, off);
        a3.x += __shfl_xor_sync(0xffffffffu, a3.x, off);
        a3.y += __shfl_xor_sync(0xffffffffu, a3.y, off);
        a3.z += __shfl_xor_sync(0xffffffffu, a3.z, off);
        a3.w += __shfl_xor_sync(0xffffffffu, a3.w, off);
    }

    if (kq == 0) {
        float* op = Out + (size_t)node * D + h * HD;
        *(float4*)(op + 0)  = a0;
        *(float4*)(op + 4)  = a1;
        *(float4*)(op + 8)  = a2;
        *(float4*)(op + 12) = a3;
    }
}

// ---------------------------------------------------------------------------
// Launch: QKV projections (3 GEMMs) -> attention -> output projection.
// ---------------------------------------------------------------------------
extern "C" void kernel_launch(void* const* d_in, const int* in_sizes, int n_in,
                              void* d_out, int out_size)
{
    const float* x   = (const float*)d_in[0];
    const int*   nbr = (const int*)d_in[1];
    const float* Wq = (const float*)d_in[2];
    const float* bq = (const float*)d_in[3];
    const float* Wk = (const float*)d_in[4];
    const float* bk = (const float*)d_in[5];
    const float* Wv = (const float*)d_in[6];
    const float* bv = (const float*)d_in[7];
    const float* Wo = (const float*)d_in[8];
    const float* bo = (const float*)d_in[9];
    float* out = (float*)d_out;

    const int N = in_sizes[0] / D;     // 50000

    float *Qp, *Kp, *Vp, *Ap;
    cudaGetSymbolAddress((void**)&Qp, g_Q);
    cudaGetSymbolAddress((void**)&Kp, g_K);
    cudaGetSymbolAddress((void**)&Vp, g_V);
    cudaGetSymbolAddress((void**)&Ap, g_A);

    const int gemmBlocks = (N + 127) / 128;
    gemm_bias_128<<<gemmBlocks, 256>>>(x, Wq, bq, Qp, N);
    gemm_bias_128<<<gemmBlocks, 256>>>(x, Wk, bk, Kp, N);
    gemm_bias_128<<<gemmBlocks, 256>>>(x, Wv, bv, Vp, N);

    const int attnBlocks = (N + 7) / 8;    // 8 warps per 256-thread block
    attn_kernel<<<attnBlocks, 256>>>(Qp, Kp, Vp, nbr, Ap, N);

    gemm_bias_128<<<gemmBlocks, 256>>>(Ap, Wo, bo, out, N);
}

// round 5
// speedup vs baseline: 1.6728x; 1.6728x over previous
#include <cuda_runtime.h>
#include <cstdint>

#define D      128
#define KN     16
#define MPAD   50048   // 391 * 128

// Scratch (device globals; allocation is forbidden)
__device__ float g_Q[(size_t)MPAD * D];
__device__ float g_K[(size_t)MPAD * D];
__device__ float g_V[(size_t)MPAD * D];
__device__ float g_A[(size_t)MPAD * D];

// ---------------------------------------------------------------------------
// tf32 helpers (sm_80+ — compiles on base sm_100 target)
// ---------------------------------------------------------------------------
__device__ __forceinline__ uint32_t f2tf32(float f) {
    uint32_t u;
    asm("cvt.rna.tf32.f32 %0, %1;" : "=r"(u) : "f"(f));
    return u;
}

__device__ __forceinline__ void mma_tf32(float* c, const uint32_t* a, const uint32_t* b) {
    asm volatile(
        "mma.sync.aligned.m16n8k8.row.col.f32.tf32.tf32.f32 "
        "{%0,%1,%2,%3}, {%4,%5,%6,%7}, {%8,%9}, {%0,%1,%2,%3};"
        : "+f"(c[0]), "+f"(c[1]), "+f"(c[2]), "+f"(c[3])
        : "r"(a[0]), "r"(a[1]), "r"(a[2]), "r"(a[3]), "r"(b[0]), "r"(b[1]));
}

#define SM_STRIDE 132                       // uint32 row stride (bank-conflict-free frags)
#define SMEM_SZ   (2 * 128 * SM_STRIDE * 4) // A tile + B tile

// ---------------------------------------------------------------------------
// Tensor-core tf32 GEMM + bias: C[M,128] = A[M,128] @ W[128,128] + b
// 128x128 CTA tile, 256 threads (8 warps of 32x64), K=128 resident in smem.
// blockIdx.y selects (W, bias, C) set so QKV is one launch.
// ---------------------------------------------------------------------------
__global__ __launch_bounds__(256, 1)
void gemm_mma(const float* __restrict__ A,
              const float* __restrict__ W0, const float* __restrict__ W1,
              const float* __restrict__ W2,
              const float* __restrict__ b0, const float* __restrict__ b1,
              const float* __restrict__ b2,
              float* __restrict__ C0, float* __restrict__ C1, float* __restrict__ C2,
              int M)
{
    extern __shared__ uint32_t sm[];
    uint32_t* As = sm;                       // As[m][k], stride 132
    uint32_t* Bs = sm + 128 * SM_STRIDE;     // Bs[n][k], stride 132  (B = W^T)

    const int tid = threadIdx.x;
    const int wid = tid >> 5;
    const int lid = tid & 31;
    const int g   = lid >> 2;                // group id 0..7
    const int t   = lid & 3;                 // thread-in-group 0..3
    const int rowBase = blockIdx.x * 128;

    const float* W    = (blockIdx.y == 0) ? W0 : (blockIdx.y == 1) ? W1 : W2;
    const float* bias = (blockIdx.y == 0) ? b0 : (blockIdx.y == 1) ? b1 : b2;
    float*       C    = (blockIdx.y == 0) ? C0 : (blockIdx.y == 1) ? C1 : C2;

    // ---- Fill A tile [128 x 128] (tf32-converted) ----
#pragma unroll
    for (int i = 0; i < 16; i++) {
        int idx = tid + i * 256;             // float4 index
        int m   = idx >> 5;
        int k4  = (idx & 31) << 2;
        float4 v = make_float4(0.f, 0.f, 0.f, 0.f);
        int gm = rowBase + m;
        if (gm < M) v = *(const float4*)(A + (size_t)gm * D + k4);
        uint32_t* p = As + m * SM_STRIDE + k4;
        p[0] = f2tf32(v.x); p[1] = f2tf32(v.y);
        p[2] = f2tf32(v.z); p[3] = f2tf32(v.w);
    }
    // ---- Fill B tile: Bs[n][k] = tf32(W[k][n]) ----
#pragma unroll
    for (int i = 0; i < 64; i++) {
        int idx = tid + i * 256;
        int k = idx >> 7;
        int n = idx & 127;
        Bs[n * SM_STRIDE + k] = f2tf32(W[(size_t)k * D + n]);
    }
    __syncthreads();

    // ---- Warp tile 32x64: warp_m = (wid&3)*32, warp_n = (wid>>2)*64 ----
    const int warp_m = (wid & 3) * 32;
    const int warp_n = (wid >> 2) * 64;

    float acc[2][8][4];
#pragma unroll
    for (int mt = 0; mt < 2; mt++)
#pragma unroll
        for (int nt = 0; nt < 8; nt++)
#pragma unroll
            for (int j = 0; j < 4; j++) acc[mt][nt][j] = 0.f;

#pragma unroll
    for (int ks = 0; ks < 16; ks++) {
        const int k0 = ks * 8;
        uint32_t af[2][4];
#pragma unroll
        for (int mt = 0; mt < 2; mt++) {
            int r0 = warp_m + mt * 16 + g;
            af[mt][0] = As[r0 * SM_STRIDE + k0 + t];
            af[mt][1] = As[(r0 + 8) * SM_STRIDE + k0 + t];
            af[mt][2] = As[r0 * SM_STRIDE + k0 + t + 4];
            af[mt][3] = As[(r0 + 8) * SM_STRIDE + k0 + t + 4];
        }
        uint32_t bf[8][2];
#pragma unroll
        for (int nt = 0; nt < 8; nt++) {
            int n = warp_n + nt * 8 + g;
            bf[nt][0] = Bs[n * SM_STRIDE + k0 + t];
            bf[nt][1] = Bs[n * SM_STRIDE + k0 + t + 4];
        }
#pragma unroll
        for (int mt = 0; mt < 2; mt++)
#pragma unroll
            for (int nt = 0; nt < 8; nt++)
                mma_tf32(acc[mt][nt], af[mt], bf[nt]);
    }

    // ---- Epilogue: registers -> global (float2 + bias), no smem round-trip ----
#pragma unroll
    for (int nt = 0; nt < 8; nt++) {
        int col = warp_n + nt * 8 + 2 * t;
        float bx = __ldg(bias + col);
        float by = __ldg(bias + col + 1);
#pragma unroll
        for (int mt = 0; mt < 2; mt++) {
            int gm = rowBase + warp_m + mt * 16 + g;
            if (gm < M) {
                float2 o = make_float2(acc[mt][nt][0] + bx, acc[mt][nt][1] + by);
                *(float2*)(C + (size_t)gm * D + col) = o;
            }
            if (gm + 8 < M) {
                float2 o = make_float2(acc[mt][nt][2] + bx, acc[mt][nt][3] + by);
                *(float2*)(C + (size_t)(gm + 8) * D + col) = o;
            }
        }
    }
}

// ---------------------------------------------------------------------------
// Neighborhood attention: one warp per node (unchanged — passing at 110us).
// ---------------------------------------------------------------------------
__global__ __launch_bounds__(256)
void attn_kernel(const float* __restrict__ Q, const float* __restrict__ Km,
                 const float* __restrict__ Vm,
                 const int* __restrict__ nbr,
                 float* __restrict__ Out, int N)
{
    const int warp = (blockIdx.x * blockDim.x + threadIdx.x) >> 5;
    if (warp >= N) return;
    const int lane = threadIdx.x & 31;
    const int h  = lane >> 2;
    const int kq = lane & 3;
    const int node = warp;

    const float* qp = Q + (size_t)node * D + h * 16;
    float4 q0 = *(const float4*)(qp + 0);
    float4 q1 = *(const float4*)(qp + 4);
    float4 q2 = *(const float4*)(qp + 8);
    float4 q3 = *(const float4*)(qp + 12);

    float s[4];
    int   ids[4];
#pragma unroll
    for (int j = 0; j < 4; j++) {
        int kk = kq * 4 + j;
        int id = nbr[(size_t)node * KN + kk];
        bool masked = (id < 0);
        int cid = id < 0 ? 0 : (id >= N ? N - 1 : id);
        ids[j] = cid;
        if (masked) {
            s[j] = -1e9f;
        } else {
            const float* kp = Km + (size_t)cid * D + h * 16;
            float4 k0 = *(const float4*)(kp + 0);
            float4 k1 = *(const float4*)(kp + 4);
            float4 k2 = *(const float4*)(kp + 8);
            float4 k3 = *(const float4*)(kp + 12);
            float d = q0.x * k0.x + q0.y * k0.y + q0.z * k0.z + q0.w * k0.w
                    + q1.x * k1.x + q1.y * k1.y + q1.z * k1.z + q1.w * k1.w
                    + q2.x * k2.x + q2.y * k2.y + q2.z * k2.z + q2.w * k2.w
                    + q3.x * k3.x + q3.y * k3.y + q3.z * k3.z + q3.w * k3.w;
            s[j] = d * 0.25f;
        }
    }

    float m = fmaxf(fmaxf(s[0], s[1]), fmaxf(s[2], s[3]));
    m = fmaxf(m, __shfl_xor_sync(0xffffffffu, m, 1));
    m = fmaxf(m, __shfl_xor_sync(0xffffffffu, m, 2));

    float e[4];
    float sum = 0.f;
#pragma unroll
    for (int j = 0; j < 4; j++) { e[j] = __expf(s[j] - m); sum += e[j]; }
    sum += __shfl_xor_sync(0xffffffffu, sum, 1);
    sum += __shfl_xor_sync(0xffffffffu, sum, 2);
    const float inv = 1.0f / sum;

    float4 a0 = make_float4(0.f, 0.f, 0.f, 0.f);
    float4 a1 = a0, a2 = a0, a3 = a0;
#pragma unroll
    for (int j = 0; j < 4; j++) {
        float w = e[j] * inv;
        const float* vp = Vm + (size_t)ids[j] * D + h * 16;
        float4 v0 = *(const float4*)(vp + 0);
        float4 v1 = *(const float4*)(vp + 4);
        float4 v2 = *(const float4*)(vp + 8);
        float4 v3 = *(const float4*)(vp + 12);
        a0.x = fmaf(w, v0.x, a0.x); a0.y = fmaf(w, v0.y, a0.y);
        a0.z = fmaf(w, v0.z, a0.z); a0.w = fmaf(w, v0.w, a0.w);
        a1.x = fmaf(w, v1.x, a1.x); a1.y = fmaf(w, v1.y, a1.y);
        a1.z = fmaf(w, v1.z, a1.z); a1.w = fmaf(w, v1.w, a1.w);
        a2.x = fmaf(w, v2.x, a2.x); a2.y = fmaf(w, v2.y, a2.y);
        a2.z = fmaf(w, v2.z, a2.z); a2.w = fmaf(w, v2.w, a2.w);
        a3.x = fmaf(w, v3.x, a3.x); a3.y = fmaf(w, v3.y, a3.y);
        a3.z = fmaf(w, v3.z, a3.z); a3.w = fmaf(w, v3.w, a3.w);
    }

#pragma unroll
    for (int off = 1; off <= 2; off <<= 1) {
        a0.x += __shfl_xor_sync(0xffffffffu, a0.x, off);
        a0.y += __shfl_xor_sync(0xffffffffu, a0.y, off);
        a0.z += __shfl_xor_sync(0xffffffffu, a0.z, off);
        a0.w += __shfl_xor_sync(0xffffffffu, a0.w, off);
        a1.x += __shfl_xor_sync(0xffffffffu, a1.x, off);
        a1.y += __shfl_xor_sync(0xffffffffu, a1.y, off);
        a1.z += __shfl_xor_sync(0xffffffffu, a1.z, off);
        a1.w += __shfl_xor_sync(0xffffffffu, a1.w, off);
        a2.x += __shfl_xor_sync(0xffffffffu, a2.x, off);
        a2.y += __shfl_xor_sync(0xffffffffu, a2.y, off);
        a2.z += __shfl_xor_sync(0xffffffffu, a2.z, off);
        a2.w += __shfl_xor_sync(0xffffffffu, a2.w, off);
        a3.x += __shfl_xor_sync(0xffffffffu, a3.x, off);
        a3.y += __shfl_xor_sync(0xffffffffu, a3.y, off);
        a3.z += __shfl_xor_sync(0xffffffffu, a3.z, off);
        a3.w += __shfl_xor_sync(0xffffffffu, a3.w, off);
    }

    if (kq == 0) {
        float* op = Out + (size_t)node * D + h * 16;
        *(float4*)(op + 0)  = a0;
        *(float4*)(op + 4)  = a1;
        *(float4*)(op + 8)  = a2;
        *(float4*)(op + 12) = a3;
    }
}

// ---------------------------------------------------------------------------
extern "C" void kernel_launch(void* const* d_in, const int* in_sizes, int n_in,
                              void* d_out, int out_size)
{
    const float* x   = (const float*)d_in[0];
    const int*   nbr = (const int*)d_in[1];
    const float* Wq = (const float*)d_in[2];
    const float* bq = (const float*)d_in[3];
    const float* Wk = (const float*)d_in[4];
    const float* bk = (const float*)d_in[5];
    const float* Wv = (const float*)d_in[6];
    const float* bv = (const float*)d_in[7];
    const float* Wo = (const float*)d_in[8];
    const float* bo = (const float*)d_in[9];
    float* out = (float*)d_out;

    const int N = in_sizes[0] / D;     // 50000

    float *Qp, *Kp, *Vp, *Ap;
    cudaGetSymbolAddress((void**)&Qp, g_Q);
    cudaGetSymbolAddress((void**)&Kp, g_K);
    cudaGetSymbolAddress((void**)&Vp, g_V);
    cudaGetSymbolAddress((void**)&Ap, g_A);

    cudaFuncSetAttribute(gemm_mma, cudaFuncAttributeMaxDynamicSharedMemorySize, SMEM_SZ);

    const int tiles = (N + 127) / 128;

    // QKV projections in one launch (y = which projection)
    gemm_mma<<<dim3(tiles, 3), 256, SMEM_SZ>>>(x, Wq, Wk, Wv, bq, bk, bv,
                                               Qp, Kp, Vp, N);

    const int attnBlocks = (N + 7) / 8;
    attn_kernel<<<attnBlocks, 256>>>(Qp, Kp, Vp, nbr, Ap, N);

    // Output projection
    gemm_mma<<<dim3(tiles, 1), 256, SMEM_SZ>>>(Ap, Wo, Wo, Wo, bo, bo, bo,
                                               out, out, out, N);
}

// round 7
// speedup vs baseline: 1.9675x; 1.1762x over previous
#include <cuda_runtime.h>
#include <cstdint>

#define D      128
#define KN     16
#define MPAD   50048   // 391 * 128

// Scratch (device globals; allocation is forbidden)
__device__ float g_Q[(size_t)MPAD * D];
__device__ float g_K[(size_t)MPAD * D];
__device__ float g_V[(size_t)MPAD * D];
__device__ float g_A[(size_t)MPAD * D];

// ---------------------------------------------------------------------------
// tf32 helpers (sm_80+ — compiles on base sm_100 target)
// ---------------------------------------------------------------------------
__device__ __forceinline__ uint32_t f2tf32(float f) {
    uint32_t u;
    asm("cvt.rna.tf32.f32 %0, %1;" : "=r"(u) : "f"(f));
    return u;
}

__device__ __forceinline__ void mma_tf32(float* c, const uint32_t* a, const uint32_t* b) {
    asm volatile(
        "mma.sync.aligned.m16n8k8.row.col.f32.tf32.tf32.f32 "
        "{%0,%1,%2,%3}, {%4,%5,%6,%7}, {%8,%9}, {%0,%1,%2,%3};"
        : "+f"(c[0]), "+f"(c[1]), "+f"(c[2]), "+f"(c[3])
        : "r"(a[0]), "r"(a[1]), "r"(a[2]), "r"(a[3]), "r"(b[0]), "r"(b[1]));
}

#define SM_STRIDE 132                       // uint32 row stride (bank-conflict-free frags)
#define SMEM_SZ   (2 * 128 * SM_STRIDE * 4) // A tile + B tile

// ---------------------------------------------------------------------------
// Tensor-core tf32 GEMM + bias: C[M,128] = A[M,128] @ W[128,128] + b
// 128x128 CTA tile, 512 threads / 16 warps (warp tile 16x64), K=128 in smem.
// blockIdx.y selects (W, bias, C) set so QKV is one launch.
// ---------------------------------------------------------------------------
__global__ __launch_bounds__(512, 1)
void gemm_mma(const float* __restrict__ A,
              const float* __restrict__ W0, const float* __restrict__ W1,
              const float* __restrict__ W2,
              const float* __restrict__ b0, const float* __restrict__ b1,
              const float* __restrict__ b2,
              float* __restrict__ C0, float* __restrict__ C1, float* __restrict__ C2,
              int M)
{
    extern __shared__ uint32_t sm[];
    uint32_t* As = sm;                       // As[m][k], stride 132
    uint32_t* Bs = sm + 128 * SM_STRIDE;     // Bs[n][k], stride 132  (B = W^T)

    const int tid = threadIdx.x;
    const int wid = tid >> 5;
    const int lid = tid & 31;
    const int g   = lid >> 2;                // group id 0..7
    const int t   = lid & 3;                 // thread-in-group 0..3
    const int rowBase = blockIdx.x * 128;

    const float* W    = (blockIdx.y == 0) ? W0 : (blockIdx.y == 1) ? W1 : W2;
    const float* bias = (blockIdx.y == 0) ? b0 : (blockIdx.y == 1) ? b1 : b2;
    float*       C    = (blockIdx.y == 0) ? C0 : (blockIdx.y == 1) ? C1 : C2;

    // ---- Fill A tile [128 x 128] (tf32-converted) ----
#pragma unroll
    for (int i = 0; i < 8; i++) {
        int idx = tid + i * 512;             // float4 index
        int m   = idx >> 5;
        int k4  = (idx & 31) << 2;
        float4 v = make_float4(0.f, 0.f, 0.f, 0.f);
        int gm = rowBase + m;
        if (gm < M) v = *(const float4*)(A + (size_t)gm * D + k4);
        uint32_t* p = As + m * SM_STRIDE + k4;
        p[0] = f2tf32(v.x); p[1] = f2tf32(v.y);
        p[2] = f2tf32(v.z); p[3] = f2tf32(v.w);
    }
    // ---- Fill B tile: Bs[n][k] = tf32(W[k][n]) ----
#pragma unroll
    for (int i = 0; i < 32; i++) {
        int idx = tid + i * 512;
        int k = idx >> 7;
        int n = idx & 127;
        Bs[n * SM_STRIDE + k] = f2tf32(W[(size_t)k * D + n]);
    }
    __syncthreads();

    // ---- Warp tile 16x64: warp_m = (wid&7)*16, warp_n = (wid>>3)*64 ----
    const int warp_m = (wid & 7) * 16;
    const int warp_n = (wid >> 3) * 64;

    float acc[8][4];
#pragma unroll
    for (int nt = 0; nt < 8; nt++)
#pragma unroll
        for (int j = 0; j < 4; j++) acc[nt][j] = 0.f;

#pragma unroll
    for (int ks = 0; ks < 16; ks++) {
        const int k0 = ks * 8;
        uint32_t af[4];
        {
            int r0 = warp_m + g;
            af[0] = As[r0 * SM_STRIDE + k0 + t];
            af[1] = As[(r0 + 8) * SM_STRIDE + k0 + t];
            af[2] = As[r0 * SM_STRIDE + k0 + t + 4];
            af[3] = As[(r0 + 8) * SM_STRIDE + k0 + t + 4];
        }
        uint32_t bf[8][2];
#pragma unroll
        for (int nt = 0; nt < 8; nt++) {
            int n = warp_n + nt * 8 + g;
            bf[nt][0] = Bs[n * SM_STRIDE + k0 + t];
            bf[nt][1] = Bs[n * SM_STRIDE + k0 + t + 4];
        }
#pragma unroll
        for (int nt = 0; nt < 8; nt++)
            mma_tf32(acc[nt], af, bf[nt]);
    }

    // ---- Epilogue: registers -> global (float2 + bias) ----
#pragma unroll
    for (int nt = 0; nt < 8; nt++) {
        int col = warp_n + nt * 8 + 2 * t;
        float bx = __ldg(bias + col);
        float by = __ldg(bias + col + 1);
        int gm = rowBase + warp_m + g;
        if (gm < M) {
            float2 o = make_float2(acc[nt][0] + bx, acc[nt][1] + by);
            *(float2*)(C + (size_t)gm * D + col) = o;
        }
        if (gm + 8 < M) {
            float2 o = make_float2(acc[nt][2] + bx, acc[nt][3] + by);
            *(float2*)(C + (size_t)(gm + 8) * D + col) = o;
        }
    }
}

// ---------------------------------------------------------------------------
// Neighborhood attention v2: one warp per node, ROW-DISTRIBUTED lanes.
// Lane l owns elements [l*4, l*4+4) of every 128-float row -> every K/V row
// gather is one fully-coalesced 512B LDG.128 (4 lines).
// Head h = lanes 4h..4h+3; head-dot via shfl.xor(1,2); softmax lane-local.
// ---------------------------------------------------------------------------
__global__ __launch_bounds__(256)
void attn_kernel(const float* __restrict__ Q, const float* __restrict__ Km,
                 const float* __restrict__ Vm,
                 const int* __restrict__ nbr,
                 float* __restrict__ Out, int N)
{
    const int warp = (blockIdx.x * blockDim.x + threadIdx.x) >> 5;
    if (warp >= N) return;
    const int lane = threadIdx.x & 31;
    const int node = warp;

    // Q row, element-distributed: lane l holds q[l*4 .. l*4+3]
    float4 q4 = *(const float4*)(Q + (size_t)node * D + lane * 4);
    q4.x *= 0.25f; q4.y *= 0.25f; q4.z *= 0.25f; q4.w *= 0.25f; // fold 1/sqrt(16)

    // neighbor ids: lane (l&15) holds id[l&15]
    int my_id = nbr[(size_t)node * KN + (lane & 15)];

    float s[KN];
#pragma unroll
    for (int j = 0; j < KN; j++) {
        int id = __shfl_sync(0xffffffffu, my_id, j);
        int cid = id < 0 ? 0 : (id >= N ? N - 1 : id);
        float4 k4 = *(const float4*)(Km + (size_t)cid * D + lane * 4);
        float p = q4.x * k4.x + q4.y * k4.y + q4.z * k4.z + q4.w * k4.w;
        // reduce within the 4 lanes of this head
        p += __shfl_xor_sync(0xffffffffu, p, 1);
        p += __shfl_xor_sync(0xffffffffu, p, 2);
        s[j] = (id < 0) ? -1e9f : p;
    }

    // softmax over 16 neighbors (lane-local: lane holds all scores of its head)
    float m = s[0];
#pragma unroll
    for (int j = 1; j < KN; j++) m = fmaxf(m, s[j]);
    float sum = 0.f;
#pragma unroll
    for (int j = 0; j < KN; j++) { s[j] = __expf(s[j] - m); sum += s[j]; }
    const float inv = 1.0f / sum;

    float4 acc = make_float4(0.f, 0.f, 0.f, 0.f);
#pragma unroll
    for (int j = 0; j < KN; j++) {
        int id = __shfl_sync(0xffffffffu, my_id, j);
        int cid = id < 0 ? 0 : (id >= N ? N - 1 : id);
        float w = s[j] * inv;               // 0 for masked (exp underflow)
        float4 v4 = *(const float4*)(Vm + (size_t)cid * D + lane * 4);
        acc.x = fmaf(w, v4.x, acc.x);
        acc.y = fmaf(w, v4.y, acc.y);
        acc.z = fmaf(w, v4.z, acc.z);
        acc.w = fmaf(w, v4.w, acc.w);
    }

    *(float4*)(Out + (size_t)node * D + lane * 4) = acc;
}

// ---------------------------------------------------------------------------
extern "C" void kernel_launch(void* const* d_in, const int* in_sizes, int n_in,
                              void* d_out, int out_size)
{
    const float* x   = (const float*)d_in[0];
    const int*   nbr = (const int*)d_in[1];
    const float* Wq = (const float*)d_in[2];
    const float* bq = (const float*)d_in[3];
    const float* Wk = (const float*)d_in[4];
    const float* bk = (const float*)d_in[5];
    const float* Wv = (const float*)d_in[6];
    const float* bv = (const float*)d_in[7];
    const float* Wo = (const float*)d_in[8];
    const float* bo = (const float*)d_in[9];
    float* out = (float*)d_out;

    const int N = in_sizes[0] / D;     // 50000

    float *Qp, *Kp, *Vp, *Ap;
    cudaGetSymbolAddress((void**)&Qp, g_Q);
    cudaGetSymbolAddress((void**)&Kp, g_K);
    cudaGetSymbolAddress((void**)&Vp, g_V);
    cudaGetSymbolAddress((void**)&Ap, g_A);

    cudaFuncSetAttribute(gemm_mma, cudaFuncAttributeMaxDynamicSharedMemorySize, SMEM_SZ);

    const int tiles = (N + 127) / 128;

    // QKV projections in one launch (y = which projection)
    gemm_mma<<<dim3(tiles, 3), 512, SMEM_SZ>>>(x, Wq, Wk, Wv, bq, bk, bv,
                                               Qp, Kp, Vp, N);

    const int attnBlocks = (N + 7) / 8;
    attn_kernel<<<attnBlocks, 256>>>(Qp, Kp, Vp, nbr, Ap, N);

    // Output projection
    gemm_mma<<<dim3(tiles, 1), 512, SMEM_SZ>>>(Ap, Wo, Wo, Wo, bo, bo, bo,
                                               out, out, out, N);
}

// round 8
// speedup vs baseline: 2.2864x; 1.1621x over previous
#include <cuda_runtime.h>
#include <cuda_bf16.h>
#include <cstdint>

#define D      128
#define KN     16
#define MPAD   50048   // 391 * 128

// Scratch (device globals; allocation is forbidden)
__device__ float g_Q[(size_t)MPAD * D];
__device__ float g_K[(size_t)MPAD * D];   // used as bf16 buffer (aliased)
__device__ float g_V[(size_t)MPAD * D];
__device__ float g_A[(size_t)MPAD * D];

// ---------------------------------------------------------------------------
// tf32 helpers (sm_80+ — compiles on base sm_100 target)
// ---------------------------------------------------------------------------
__device__ __forceinline__ uint32_t f2tf32(float f) {
    uint32_t u;
    asm("cvt.rna.tf32.f32 %0, %1;" : "=r"(u) : "f"(f));
    return u;
}

__device__ __forceinline__ void mma_tf32(float* c, const uint32_t* a, const uint32_t* b) {
    asm volatile(
        "mma.sync.aligned.m16n8k8.row.col.f32.tf32.tf32.f32 "
        "{%0,%1,%2,%3}, {%4,%5,%6,%7}, {%8,%9}, {%0,%1,%2,%3};"
        : "+f"(c[0]), "+f"(c[1]), "+f"(c[2]), "+f"(c[3])
        : "r"(a[0]), "r"(a[1]), "r"(a[2]), "r"(a[3]), "r"(b[0]), "r"(b[1]));
}

#define SM_STRIDE 132                       // uint32 row stride (bank-conflict-free frags)
#define SMEM_SZ   (2 * 128 * SM_STRIDE * 4) // A tile + B tile

// ---------------------------------------------------------------------------
// Tensor-core tf32 GEMM + bias: C[M,128] = A[M,128] @ W[128,128] + b
// 128x128 CTA tile, 256 threads / 8 warps (warp tile 32x64 — R4 proven config).
// blockIdx.y selects (W, bias, C) set; y==1 (K projection) writes bf16 to Kb.
// ---------------------------------------------------------------------------
__global__ __launch_bounds__(256, 1)
void gemm_mma(const float* __restrict__ A,
              const float* __restrict__ W0, const float* __restrict__ W1,
              const float* __restrict__ W2,
              const float* __restrict__ b0, const float* __restrict__ b1,
              const float* __restrict__ b2,
              float* __restrict__ C0, __nv_bfloat16* __restrict__ Kb,
              float* __restrict__ C2,
              int M)
{
    extern __shared__ uint32_t sm[];
    uint32_t* As = sm;                       // As[m][k], stride 132
    uint32_t* Bs = sm + 128 * SM_STRIDE;     // Bs[n][k], stride 132  (B = W^T)

    const int tid = threadIdx.x;
    const int wid = tid >> 5;
    const int lid = tid & 31;
    const int g   = lid >> 2;                // group id 0..7
    const int t   = lid & 3;                 // thread-in-group 0..3
    const int rowBase = blockIdx.x * 128;

    const float* W    = (blockIdx.y == 0) ? W0 : (blockIdx.y == 1) ? W1 : W2;
    const float* bias = (blockIdx.y == 0) ? b0 : (blockIdx.y == 1) ? b1 : b2;

    // ---- Fill A tile [128 x 128] (tf32-converted) ----
#pragma unroll
    for (int i = 0; i < 16; i++) {
        int idx = tid + i * 256;             // float4 index
        int m   = idx >> 5;
        int k4  = (idx & 31) << 2;
        float4 v = make_float4(0.f, 0.f, 0.f, 0.f);
        int gm = rowBase + m;
        if (gm < M) v = *(const float4*)(A + (size_t)gm * D + k4);
        uint32_t* p = As + m * SM_STRIDE + k4;
        p[0] = f2tf32(v.x); p[1] = f2tf32(v.y);
        p[2] = f2tf32(v.z); p[3] = f2tf32(v.w);
    }
    // ---- Fill B tile: Bs[n][k] = tf32(W[k][n]) ----
#pragma unroll
    for (int i = 0; i < 64; i++) {
        int idx = tid + i * 256;
        int k = idx >> 7;
        int n = idx & 127;
        Bs[n * SM_STRIDE + k] = f2tf32(W[(size_t)k * D + n]);
    }
    __syncthreads();

    // ---- Warp tile 32x64: warp_m = (wid&3)*32, warp_n = (wid>>2)*64 ----
    const int warp_m = (wid & 3) * 32;
    const int warp_n = (wid >> 2) * 64;

    float acc[2][8][4];
#pragma unroll
    for (int mt = 0; mt < 2; mt++)
#pragma unroll
        for (int nt = 0; nt < 8; nt++)
#pragma unroll
            for (int j = 0; j < 4; j++) acc[mt][nt][j] = 0.f;

#pragma unroll
    for (int ks = 0; ks < 16; ks++) {
        const int k0 = ks * 8;
        uint32_t af[2][4];
#pragma unroll
        for (int mt = 0; mt < 2; mt++) {
            int r0 = warp_m + mt * 16 + g;
            af[mt][0] = As[r0 * SM_STRIDE + k0 + t];
            af[mt][1] = As[(r0 + 8) * SM_STRIDE + k0 + t];
            af[mt][2] = As[r0 * SM_STRIDE + k0 + t + 4];
            af[mt][3] = As[(r0 + 8) * SM_STRIDE + k0 + t + 4];
        }
        uint32_t bf[8][2];
#pragma unroll
        for (int nt = 0; nt < 8; nt++) {
            int n = warp_n + nt * 8 + g;
            bf[nt][0] = Bs[n * SM_STRIDE + k0 + t];
            bf[nt][1] = Bs[n * SM_STRIDE + k0 + t + 4];
        }
#pragma unroll
        for (int mt = 0; mt < 2; mt++)
#pragma unroll
            for (int nt = 0; nt < 8; nt++)
                mma_tf32(acc[mt][nt], af[mt], bf[nt]);
    }

    // ---- Epilogue ----
    if (blockIdx.y == 1) {
        // K projection: write bf16 (attn reads K as bf16; halves gather bytes)
#pragma unroll
        for (int nt = 0; nt < 8; nt++) {
            int col = warp_n + nt * 8 + 2 * t;
            float bx = __ldg(bias + col);
            float by = __ldg(bias + col + 1);
            int gm = rowBase + warp_m + g;
            if (gm < M) {
                *(__nv_bfloat162*)(Kb + (size_t)gm * D + col) =
                    __floats2bfloat162_rn(acc[0][nt][0] + bx, acc[0][nt][1] + by);
            }
            if (gm + 8 < M) {
                *(__nv_bfloat162*)(Kb + (size_t)(gm + 8) * D + col) =
                    __floats2bfloat162_rn(acc[0][nt][2] + bx, acc[0][nt][3] + by);
            }
            int gm2 = gm + 16;
            if (gm2 < M) {
                *(__nv_bfloat162*)(Kb + (size_t)gm2 * D + col) =
                    __floats2bfloat162_rn(acc[1][nt][0] + bx, acc[1][nt][1] + by);
            }
            if (gm2 + 8 < M) {
                *(__nv_bfloat162*)(Kb + (size_t)(gm2 + 8) * D + col) =
                    __floats2bfloat162_rn(acc[1][nt][2] + bx, acc[1][nt][3] + by);
            }
        }
    } else {
        float* C = (blockIdx.y == 0) ? C0 : C2;
#pragma unroll
        for (int nt = 0; nt < 8; nt++) {
            int col = warp_n + nt * 8 + 2 * t;
            float bx = __ldg(bias + col);
            float by = __ldg(bias + col + 1);
#pragma unroll
            for (int mt = 0; mt < 2; mt++) {
                int gm = rowBase + warp_m + mt * 16 + g;
                if (gm < M) {
                    float2 o = make_float2(acc[mt][nt][0] + bx, acc[mt][nt][1] + by);
                    *(float2*)(C + (size_t)gm * D + col) = o;
                }
                if (gm + 8 < M) {
                    float2 o = make_float2(acc[mt][nt][2] + bx, acc[mt][nt][3] + by);
                    *(float2*)(C + (size_t)(gm + 8) * D + col) = o;
                }
            }
        }
    }
}

// ---------------------------------------------------------------------------
// Neighborhood attention v3: one warp per node, row-distributed lanes.
// K rows are bf16 (256B/row -> 8B/lane coalesced); V rows fp32.
// ---------------------------------------------------------------------------
__global__ __launch_bounds__(256)
void attn_kernel(const float* __restrict__ Q,
                 const __nv_bfloat16* __restrict__ Kb,
                 const float* __restrict__ Vm,
                 const int* __restrict__ nbr,
                 float* __restrict__ Out, int N)
{
    const int warp = (blockIdx.x * blockDim.x + threadIdx.x) >> 5;
    if (warp >= N) return;
    const int lane = threadIdx.x & 31;
    const int node = warp;

    // Q row, element-distributed: lane l holds q[l*4 .. l*4+3]
    float4 q4 = *(const float4*)(Q + (size_t)node * D + lane * 4);
    q4.x *= 0.25f; q4.y *= 0.25f; q4.z *= 0.25f; q4.w *= 0.25f; // fold 1/sqrt(16)

    // neighbor ids: lane (l&15) holds id[l&15]
    int my_id = nbr[(size_t)node * KN + (lane & 15)];

    float s[KN];
#pragma unroll
    for (int j = 0; j < KN; j++) {
        int id = __shfl_sync(0xffffffffu, my_id, j);
        int cid = id < 0 ? 0 : (id >= N ? N - 1 : id);
        uint2 raw = *(const uint2*)(Kb + (size_t)cid * D + lane * 4);
        float2 f0 = __bfloat1622float2(*reinterpret_cast<const __nv_bfloat162*>(&raw.x));
        float2 f1 = __bfloat1622float2(*reinterpret_cast<const __nv_bfloat162*>(&raw.y));
        float p = q4.x * f0.x + q4.y * f0.y + q4.z * f1.x + q4.w * f1.y;
        // reduce within the 4 lanes of this head
        p += __shfl_xor_sync(0xffffffffu, p, 1);
        p += __shfl_xor_sync(0xffffffffu, p, 2);
        s[j] = (id < 0) ? -1e9f : p;
    }

    // softmax over 16 neighbors (lane-local: lane holds all scores of its head)
    float m = s[0];
#pragma unroll
    for (int j = 1; j < KN; j++) m = fmaxf(m, s[j]);
    float sum = 0.f;
#pragma unroll
    for (int j = 0; j < KN; j++) { s[j] = __expf(s[j] - m); sum += s[j]; }
    const float inv = 1.0f / sum;

    float4 acc = make_float4(0.f, 0.f, 0.f, 0.f);
#pragma unroll
    for (int j = 0; j < KN; j++) {
        int id = __shfl_sync(0xffffffffu, my_id, j);
        int cid = id < 0 ? 0 : (id >= N ? N - 1 : id);
        float w = s[j] * inv;               // 0 for masked (exp underflow)
        float4 v4 = *(const float4*)(Vm + (size_t)cid * D + lane * 4);
        acc.x = fmaf(w, v4.x, acc.x);
        acc.y = fmaf(w, v4.y, acc.y);
        acc.z = fmaf(w, v4.z, acc.z);
        acc.w = fmaf(w, v4.w, acc.w);
    }

    *(float4*)(Out + (size_t)node * D + lane * 4) = acc;
}

// ---------------------------------------------------------------------------
extern "C" void kernel_launch(void* const* d_in, const int* in_sizes, int n_in,
                              void* d_out, int out_size)
{
    const float* x   = (const float*)d_in[0];
    const int*   nbr = (const int*)d_in[1];
    const float* Wq = (const float*)d_in[2];
    const float* bq = (const float*)d_in[3];
    const float* Wk = (const float*)d_in[4];
    const float* bk = (const float*)d_in[5];
    const float* Wv = (const float*)d_in[6];
    const float* bv = (const float*)d_in[7];
    const float* Wo = (const float*)d_in[8];
    const float* bo = (const float*)d_in[9];
    float* out = (float*)d_out;

    const int N = in_sizes[0] / D;     // 50000

    float *Qp, *Kp, *Vp, *Ap;
    cudaGetSymbolAddress((void**)&Qp, g_Q);
    cudaGetSymbolAddress((void**)&Kp, g_K);
    cudaGetSymbolAddress((void**)&Vp, g_V);
    cudaGetSymbolAddress((void**)&Ap, g_A);
    __nv_bfloat16* Kb = (__nv_bfloat16*)Kp;   // reuse g_K storage as bf16

    cudaFuncSetAttribute(gemm_mma, cudaFuncAttributeMaxDynamicSharedMemorySize, SMEM_SZ);

    const int tiles = (N + 127) / 128;

    // QKV projections in one launch (y: 0=Q fp32, 1=K bf16, 2=V fp32)
    gemm_mma<<<dim3(tiles, 3), 256, SMEM_SZ>>>(x, Wq, Wk, Wv, bq, bk, bv,
                                               Qp, Kb, Vp, N);

    const int attnBlocks = (N + 7) / 8;
    attn_kernel<<<attnBlocks, 256>>>(Qp, Kb, Vp, nbr, Ap, N);

    // Output projection (y==0 -> fp32 path -> out)
    gemm_mma<<<dim3(tiles, 1), 256, SMEM_SZ>>>(Ap, Wo, Wo, Wo, bo, bo, bo,
                                               out, Kb, out, N);
}